// round 1
// baseline (speedup 1.0000x reference)
#include <cuda_runtime.h>

#define NN 1024
#define HH 128

// Scratch for aggregated messages (device global: no allocation allowed)
__device__ float g_agg[NN * HH];

// ---------------------------------------------------------------------------
// Kernel 1: agg[i,h] = sum_j adj[i,j] * nf[j,h] * T[i,j,h]
// One CTA per i. 8 warps; warp w owns j in [w*128, w*128+128).
// Warp-wide float4 load covers the full 512B H-row of T and nf.
// adj gating skips the T row load entirely (halves DRAM traffic).
// ---------------------------------------------------------------------------
__global__ __launch_bounds__(256) void agg_kernel(
    const float* __restrict__ nf,
    const int*   __restrict__ adj,
    const float* __restrict__ T)
{
    const int i    = blockIdx.x;
    const int tid  = threadIdx.x;
    const int lane = tid & 31;
    const int w    = tid >> 5;          // 0..7

    __shared__ int    sadj[NN];
    __shared__ float4 sred[8][32];

    #pragma unroll
    for (int j = tid; j < NN; j += 256) sadj[j] = adj[i * NN + j];
    __syncthreads();

    const float4* nf4 = (const float4*)nf;
    const float4* T4  = (const float4*)T;

    float4 acc0 = make_float4(0.f, 0.f, 0.f, 0.f);
    float4 acc1 = make_float4(0.f, 0.f, 0.f, 0.f);

    const long rowbase = (long)i * NN;
    const int  jbeg = w * (NN / 8);

    #pragma unroll 2
    for (int j = jbeg; j < jbeg + NN / 8; j += 2) {
        if (sadj[j]) {
            float4 t = T4[(rowbase + j) * 32 + lane];
            float4 f = nf4[j * 32 + lane];
            acc0.x += f.x * t.x; acc0.y += f.y * t.y;
            acc0.z += f.z * t.z; acc0.w += f.w * t.w;
        }
        if (sadj[j + 1]) {
            float4 t = T4[(rowbase + j + 1) * 32 + lane];
            float4 f = nf4[(j + 1) * 32 + lane];
            acc1.x += f.x * t.x; acc1.y += f.y * t.y;
            acc1.z += f.z * t.z; acc1.w += f.w * t.w;
        }
    }
    acc0.x += acc1.x; acc0.y += acc1.y; acc0.z += acc1.z; acc0.w += acc1.w;

    sred[w][lane] = acc0;
    __syncthreads();

    if (tid < 32) {
        float4 s = sred[0][tid];
        #pragma unroll
        for (int ww = 1; ww < 8; ww++) {
            float4 v = sred[ww][tid];
            s.x += v.x; s.y += v.y; s.z += v.z; s.w += v.w;
        }
        ((float4*)g_agg)[i * 32 + tid] = s;
    }
}

// ---------------------------------------------------------------------------
// Kernel 2: GRU cell.
//   gi = agg @ w_ih^T + b_ih ; gh = nf @ w_hh^T + b_hh
//   r = sig(gi_r+gh_r); z = sig(gi_z+gh_z); n = tanh(gi_n + r*gh_n)
//   out = (1-z)*n + z*nf
// Block: 256 threads, tile of IT=8 rows (i), full H=128 columns.
// h = tid & 127; ty = tid >> 7 picks 4 of the 8 rows.
// Weights streamed from L2 (393 KB total, fully resident).
// ---------------------------------------------------------------------------
__global__ __launch_bounds__(256) void gru_kernel(
    const float* __restrict__ nf,
    const float* __restrict__ wih,
    const float* __restrict__ whh,
    const float* __restrict__ bih,
    const float* __restrict__ bhh,
    float*       __restrict__ out)
{
    const int IT = 8;
    const int ib  = blockIdx.x * IT;
    const int tid = threadIdx.x;
    const int h   = tid & 127;
    const int ty  = tid >> 7;        // 0/1, each handles 4 rows

    __shared__ float4 sA[IT][32];
    __shared__ float4 sH[IT][32];

    #pragma unroll
    for (int e = tid; e < IT * 32; e += 256) {
        int il = e >> 5, k4 = e & 31;
        sA[il][k4] = ((const float4*)g_agg)[(ib + il) * 32 + k4];
        sH[il][k4] = ((const float4*)nf)[(ib + il) * 32 + k4];
    }
    __syncthreads();

    const float4* wih4 = (const float4*)wih;
    const float4* whh4 = (const float4*)whh;

    float ar[4] = {0.f, 0.f, 0.f, 0.f};
    float az[4] = {0.f, 0.f, 0.f, 0.f};
    float gn[4] = {0.f, 0.f, 0.f, 0.f};
    float hn[4] = {0.f, 0.f, 0.f, 0.f};

    #pragma unroll 4
    for (int k4 = 0; k4 < 32; k4++) {
        float4 wr = wih4[(h        ) * 32 + k4];
        float4 wz = wih4[(h + 128  ) * 32 + k4];
        float4 wn = wih4[(h + 256  ) * 32 + k4];
        float4 vr = whh4[(h        ) * 32 + k4];
        float4 vz = whh4[(h + 128  ) * 32 + k4];
        float4 vn = whh4[(h + 256  ) * 32 + k4];
        #pragma unroll
        for (int il = 0; il < 4; il++) {
            int ii = ty * 4 + il;
            float4 a = sA[ii][k4];
            float4 x = sH[ii][k4];
            ar[il] += a.x * wr.x + a.y * wr.y + a.z * wr.z + a.w * wr.w
                    + x.x * vr.x + x.y * vr.y + x.z * vr.z + x.w * vr.w;
            az[il] += a.x * wz.x + a.y * wz.y + a.z * wz.z + a.w * wz.w
                    + x.x * vz.x + x.y * vz.y + x.z * vz.z + x.w * vz.w;
            gn[il] += a.x * wn.x + a.y * wn.y + a.z * wn.z + a.w * wn.w;
            hn[il] += x.x * vn.x + x.y * vn.y + x.z * vn.z + x.w * vn.w;
        }
    }

    const float br  = bih[h]       + bhh[h];
    const float bz  = bih[h + 128] + bhh[h + 128];
    const float bgn = bih[h + 256];
    const float bhn = bhh[h + 256];

    #pragma unroll
    for (int il = 0; il < 4; il++) {
        int ii = ty * 4 + il;
        float r   = ar[il] + br;
        float z   = az[il] + bz;
        float gin = gn[il] + bgn;
        float ghn = hn[il] + bhn;
        r = 1.f / (1.f + __expf(-r));
        z = 1.f / (1.f + __expf(-z));
        float nng   = tanhf(gin + r * ghn);
        float hprev = ((const float*)sH)[ii * 128 + h];
        out[(ib + ii) * 128 + h] = (1.f - z) * nng + z * hprev;
    }
}

extern "C" void kernel_launch(void* const* d_in, const int* in_sizes, int n_in,
                              void* d_out, int out_size)
{
    const float* nf  = (const float*)d_in[0];
    const int*   adj = (const int*)  d_in[1];
    const float* T   = (const float*)d_in[2];
    const float* wih = (const float*)d_in[3];
    const float* whh = (const float*)d_in[4];
    const float* bih = (const float*)d_in[5];
    const float* bhh = (const float*)d_in[6];
    float* out = (float*)d_out;

    agg_kernel<<<NN, 256>>>(nf, adj, T);
    gru_kernel<<<NN / 8, 256>>>(nf, wih, whh, bih, bhh, out);
}